// round 5
// baseline (speedup 1.0000x reference)
#include <cuda_runtime.h>
#include <math.h>

#define MM      8
#define AA      48
#define NSPEC   4
#define NPAIRCH 10
#define NSHFR   16
#define RADDIM  (NSPEC * NSHFR)            /* 64  */
#define ANGDIM  (NPAIRCH * 32)             /* 320 */
#define OUTDIM  (RADDIM + ANGDIM)          /* 384 */
#define RCR_F   5.2f
#define RCA_F   3.5f
#define PI_F    3.14159265358979323846f
#define NT      128
#define NW      4                           /* warps per block */

__global__ __launch_bounds__(NT, 1) void aev_kernel(
    const float* __restrict__ coords,   // (M, A, 3)
    const float* __restrict__ EtaR,     // (1,)
    const float* __restrict__ ShfR,     // (16,)
    const float* __restrict__ EtaA,     // (1,)
    const float* __restrict__ Zeta,     // (1,)
    const float* __restrict__ ShfA,     // (4,)
    const float* __restrict__ ShfZ,     // (8,)
    const int*   __restrict__ species,  // (M, A)
    const int*   __restrict__ triu,     // (4, 4)
    float*       __restrict__ out)      // (M, A, 384)
{
    __shared__ float4 atm[AA];              // x, y, z, species(bits)
    __shared__ float  sdd[AA], spre[AA];    // d, 0.25*fc_R (0 if invalid)
    __shared__ int    ssp[AA];
    __shared__ float4 nbrA[AA];             // ux, uy, uz, d   (RCA neighbors)
    __shared__ float2 nbrB[AA];             // fc_A, species(bits)
    __shared__ int    s_triu[NSPEC * NSPEC];
    __shared__ int    nnbr;
    __shared__ float  acc[NW][OUTDIM];      // warp-private: 64 rad + 320 ang

    const int mi   = blockIdx.x;            // env = (m, i)
    const int m    = mi / AA;
    const int i    = mi % AA;
    const int tid  = threadIdx.x;
    const int wid  = tid >> 5;
    const int lane = tid & 31;

    // per-thread parameters (tiny, L1-cached constant loads)
    const float etaR  = __ldg(EtaR);
    const float etaA  = __ldg(EtaA);
    const float zeta  = __ldg(Zeta);
    const float shfr_r = __ldg(&ShfR[lane & 15]);
    const float sha    = __ldg(&ShfA[lane >> 3]);
    const float shz    = __ldg(&ShfZ[lane & 7]);
    const float cz = __cosf(shz), sz = __sinf(shz);
    const bool  z32 = (zeta == 32.0f);

    // ---- phase 1: load + zero ----
    if (tid == 0) nnbr = 0;
    if (tid < NSPEC * NSPEC) s_triu[tid] = triu[tid];
    if (tid < AA) {
        const float* c = coords + (m * AA + tid) * 3;
        atm[tid] = make_float4(c[0], c[1], c[2],
                               __int_as_float(species[m * AA + tid]));
    }
    #pragma unroll
    for (int t = tid; t < NW * OUTDIM; t += NT)
        ((float*)acc)[t] = 0.0f;
    __syncthreads();

    // ---- phase 2: distances, radial precompute, neighbor compaction ----
    if (tid < AA) {
        float4 aj = atm[tid];
        float4 ai = atm[i];
        int   spj = __float_as_int(aj.w);
        int   spi = __float_as_int(ai.w);
        float dx = aj.x - ai.x, dy = aj.y - ai.y, dz = aj.z - ai.z;
        float d2 = dx * dx + dy * dy + dz * dz;
        float d  = sqrtf(d2 > 0.0f ? d2 : 1.0f);
        bool pvb = (spi >= 0) && (spj >= 0) && (tid != i);
        float pr = 0.0f;
        if (pvb && d <= RCR_F)
            pr = 0.25f * (0.5f * __cosf(d * (PI_F / RCR_F)) + 0.5f);
        sdd[tid]  = d;
        spre[tid] = pr;
        ssp[tid]  = spj;
        if (pvb && d <= RCA_F) {
            int   idx  = atomicAdd(&nnbr, 1);
            float rinv = 1.0f / d;
            nbrA[idx] = make_float4(dx * rinv, dy * rinv, dz * rinv, d);
            nbrB[idx] = make_float2(0.5f * __cosf(d * (PI_F / RCA_F)) + 0.5f, aj.w);
        }
    }
    __syncthreads();

    const int n = nnbr;
    float* wacc = acc[wid];

    // ---- phase 3a: radial — register accumulation, warp splits k-range ----
    {
        float a0 = 0.0f, a1 = 0.0f, a2 = 0.0f, a3 = 0.0f;
        const int hi = lane >> 4;           // which j-parity this lane covers
        #pragma unroll
        for (int k = 0; k < 6; k++) {
            int j = 12 * wid + 2 * k + hi;  // warp wid covers j in [12w, 12w+12)
            float pr = spre[j];
            float u  = sdd[j] - shfr_r;
            float v  = pr * __expf(-etaR * u * u);
            int   s  = ssp[j];
            a0 += (s == 0) ? v : 0.0f;
            a1 += (s == 1) ? v : 0.0f;
            a2 += (s == 2) ? v : 0.0f;
            a3 += (s == 3) ? v : 0.0f;
        }
        a0 += __shfl_xor_sync(0xffffffffu, a0, 16);
        a1 += __shfl_xor_sync(0xffffffffu, a1, 16);
        a2 += __shfl_xor_sync(0xffffffffu, a2, 16);
        a3 += __shfl_xor_sync(0xffffffffu, a3, 16);
        if (lane < 16) {
            wacc[0 * NSHFR + lane] = a0;
            wacc[1 * NSHFR + lane] = a1;
            wacc[2 * NSHFR + lane] = a2;
            wacc[3 * NSHFR + lane] = a3;
        }
    }

    // ---- phase 3b: angular — pairs strided across 4 warps, private acc ----
    {
        const int npairs = (n * (n - 1)) >> 1;
        // incremental (jj, kk) walk starting at linear index `wid`, stride NW
        int jj = 0, kk = 1 + wid;
        while (kk >= n && jj < n - 1) { int ov = kk - n; jj++; kk = jj + 1 + ov; }
        float* aang = wacc + RADDIM;

        for (int t = wid; t < npairs; t += NW) {
            float4 aj = nbrA[jj];
            float4 ak = nbrA[kk];
            float2 bj = nbrB[jj];
            float2 bk = nbrB[kk];
            float c = 0.95f * (aj.x * ak.x + aj.y * ak.y + aj.z * ak.z);
            c = fminf(0.99f, fmaxf(-0.99f, c));
            float s    = sqrtf(1.0f - c * c);     // sin(arccos(c)) >= 0
            float davg = 0.5f * (aj.w + ak.w);
            float fcp2 = 2.0f * bj.x * bk.x;
            int   p    = s_triu[__float_as_int(bj.y) * NSPEC + __float_as_int(bk.y)];

            // cos(theta - ShfZ) = c*cos + sin(theta)*sin
            float base = 0.5f + 0.5f * (c * cz + s * sz);
            float f1;
            if (z32) {
                float b2 = base * base;
                float b4 = b2 * b2;
                float b8 = b4 * b4;
                float b16 = b8 * b8;
                f1 = b16 * b16;
            } else {
                f1 = __powf(base, zeta);
            }
            float u  = davg - sha;
            float f2 = __expf(-etaA * u * u);
            int idx = p * 32 + lane;
            aang[idx] += f1 * f2 * fcp2;          // private: plain RMW, no atomic

            kk += NW;
            while (kk >= n && jj < n - 1) { int ov = kk - n; jj++; kk = jj + 1 + ov; }
        }
    }
    __syncthreads();

    // ---- phase 4: merge 4 warp copies and write out ----
    float* ob = out + mi * OUTDIM;
    #pragma unroll
    for (int t = tid; t < OUTDIM; t += NT)
        ob[t] = acc[0][t] + acc[1][t] + acc[2][t] + acc[3][t];
}

extern "C" void kernel_launch(void* const* d_in, const int* in_sizes, int n_in,
                              void* d_out, int out_size)
{
    const float* coordsp = (const float*)d_in[0];
    const float* etaRp   = (const float*)d_in[1];
    const float* shfRp   = (const float*)d_in[2];
    const float* etaAp   = (const float*)d_in[3];
    const float* zetap   = (const float*)d_in[4];
    const float* shfAp   = (const float*)d_in[5];
    const float* shfZp   = (const float*)d_in[6];
    const int*   specp   = (const int*)d_in[7];
    const int*   triup   = (const int*)d_in[8];
    float*       outp    = (float*)d_out;

    aev_kernel<<<MM * AA, NT>>>(coordsp, etaRp, shfRp, etaAp, zetap, shfAp,
                                shfZp, specp, triup, outp);
}